// round 4
// baseline (speedup 1.0000x reference)
#include <cuda_runtime.h>

// Problem shapes (fixed)
#define BB 32
#define NN 4096
#define DD 8
#define NEE 2048
#define DEE 4

// Device scratch (static globals; no allocation)
__device__ unsigned g_mask_int[NN];
__device__ unsigned g_mask_ext[NEE];
__device__ int g_list_int[BB][4352];
__device__ int g_list_ext[BB][2304];
__device__ int g_cnt_int[BB];
__device__ int g_cnt_ext[BB];

// ---------------------------------------------------------------------------
// Kernel 1 (fused spike + mask): thread per source column.
// For internal sources (i < N): compute X[b,i] and a_new[b,i] for all 32
// batches (coalesced: consecutive i across lanes), write out rows 0 & 2,
// build the delay-selected spike bitmask for internal sources.
// For external sources (i < NE): build the delay-selected bitmask from Xext.
// ---------------------------------------------------------------------------
__global__ void k_spike_mask(const float* __restrict__ V, const float* __restrict__ a,
                             const float* __restrict__ Xd, const float* __restrict__ Xext,
                             const float* __restrict__ dmap_int,
                             const float* __restrict__ dmap_ext,
                             float* __restrict__ out) {
    int i = blockIdx.x * blockDim.x + threadIdx.x;      // 0 .. N-1

    // --- internal ---
    {
        int del = 0;
#pragma unroll
        for (int d = 0; d < DD; d++)
            if (dmap_int[d * NN + i] > 0.5f) del = d;

        unsigned m = 0;
#pragma unroll 4
        for (int b = 0; b < BB; b++) {
            int idx = b * NN + i;
            float v  = V[idx];
            float aa = a[idx];
            float th = __fadd_rn(1.0f, __fmul_rn(1.8f, aa));
            float x  = (__fadd_rn(v, -th) >= 0.0f) ? 1.0f : 0.0f;
            out[idx] = x;                               // row 0: X
            out[2 * BB * NN + idx] = 0.98f * aa + x;    // row 2: a_new
            float xs = (del == 0) ? x : Xd[(size_t)(del - 1) * BB * NN + idx];
            if (xs > 0.5f) m |= (1u << b);
        }
        g_mask_int[i] = m;
    }

    // --- external ---
    if (i < NEE) {
        int del = 0;
#pragma unroll
        for (int d = 0; d < DEE; d++)
            if (dmap_ext[d * NEE + i] > 0.5f) del = d;
        const float* src = Xext + (size_t)del * BB * NEE + i;
        unsigned m = 0;
#pragma unroll 4
        for (int b = 0; b < BB; b++)
            if (src[b * NEE] > 0.5f) m |= (1u << b);
        g_mask_ext[i] = m;
    }
}

// ---------------------------------------------------------------------------
// Kernel 2: parallel deterministic compaction. One block (8 warps) per batch.
// Lists padded to a multiple of 16 with -1 sentinels.
// ---------------------------------------------------------------------------
__global__ void __launch_bounds__(256) k_compact() {
    int b = blockIdx.x;            // 0..31
    int tid = threadIdx.x;
    int w = tid >> 5, lane = tid & 31;
    unsigned lt = (lane == 0) ? 0u : (0xffffffffu >> (32 - lane));

    __shared__ int wcnt[8], wbase[8], s_total;

    // ---- internal: each warp owns 512 sources (16 rounds) ----
    {
        int cnt = 0;
#pragma unroll
        for (int r = 0; r < 16; r++) {
            int i = (w * 16 + r) * 32 + lane;
            bool act = (g_mask_int[i] >> b) & 1u;
            cnt += __popc(__ballot_sync(0xffffffffu, act));
        }
        if (lane == 0) wcnt[w] = cnt;
        __syncthreads();
        if (tid == 0) {
            int s = 0;
#pragma unroll
            for (int j = 0; j < 8; j++) { wbase[j] = s; s += wcnt[j]; }
            s_total = s;
        }
        __syncthreads();
        int base = wbase[w];
#pragma unroll
        for (int r = 0; r < 16; r++) {
            int i = (w * 16 + r) * 32 + lane;
            bool act = (g_mask_int[i] >> b) & 1u;
            unsigned bal = __ballot_sync(0xffffffffu, act);
            if (act) g_list_int[b][base + __popc(bal & lt)] = i;
            base += __popc(bal);
        }
        int t = s_total;
        int padded = (t + 15) & ~15;
        if (t + tid < padded) g_list_int[b][t + tid] = -1;
        if (tid == 0) g_cnt_int[b] = padded;
        __syncthreads();
    }

    // ---- external: each warp owns 256 sources (8 rounds) ----
    {
        int cnt = 0;
#pragma unroll
        for (int r = 0; r < 8; r++) {
            int i = (w * 8 + r) * 32 + lane;
            bool act = (g_mask_ext[i] >> b) & 1u;
            cnt += __popc(__ballot_sync(0xffffffffu, act));
        }
        if (lane == 0) wcnt[w] = cnt;
        __syncthreads();
        if (tid == 0) {
            int s = 0;
#pragma unroll
            for (int j = 0; j < 8; j++) { wbase[j] = s; s += wcnt[j]; }
            s_total = s;
        }
        __syncthreads();
        int base = wbase[w];
#pragma unroll
        for (int r = 0; r < 8; r++) {
            int i = (w * 8 + r) * 32 + lane;
            bool act = (g_mask_ext[i] >> b) & 1u;
            unsigned bal = __ballot_sync(0xffffffffu, act);
            if (act) g_list_ext[b][base + __popc(bal & lt)] = i;
            base += __popc(bal);
        }
        int t = s_total;
        int padded = (t + 15) & ~15;
        if (t + tid < padded) g_list_ext[b][t + tid] = -1;
        if (tid == 0) g_cnt_ext[b] = padded;
    }
}

// ---------------------------------------------------------------------------
// Kernel 3: sparse row-gather + membrane update.
// One column per thread, 128 threads/block, grid (N/128, B). launch_bounds
// (128, 4) gives ptxas up to 128 regs so the full 16-wide LDG window stays
// live (16 indices + 16 values in registers -> 16 independent LDG.32 in
// flight per thread). 4-way accumulators shorten the FADD tail.
// ---------------------------------------------------------------------------
__global__ void __launch_bounds__(128, 4) k_gather(
        const float* __restrict__ V,
        const float* __restrict__ W_int,
        const float* __restrict__ W_ext,
        float* __restrict__ out) {
    __shared__ int s_int[4352];
    __shared__ int s_ext[2304];

    int b = blockIdx.y;
    const int cnt_i = g_cnt_int[b];
    const int cnt_e = g_cnt_ext[b];
    for (int k = threadIdx.x; k < cnt_i; k += 128) s_int[k] = g_list_int[b][k];
    for (int k = threadIdx.x; k < cnt_e; k += 128) s_ext[k] = g_list_ext[b][k];
    __syncthreads();

    int n = blockIdx.x * 128 + threadIdx.x;   // column
    int idx = b * NN + n;

    float x = out[idx];                       // X (row 0)
    float acc0 = 0.95f * V[idx] * (1.0f - x);
    float acc1 = 0.0f, acc2 = 0.0f, acc3 = 0.0f;

    for (int k = 0; k < cnt_i; k += 16) {
        int e[16];
#pragma unroll
        for (int u = 0; u < 16; u++) e[u] = s_int[k + u];
        float w[16];
#pragma unroll
        for (int u = 0; u < 16; u++)
            w[u] = (e[u] >= 0) ? __ldg(W_int + (size_t)e[u] * NN + n) : 0.0f;
#pragma unroll
        for (int u = 0; u < 16; u += 4) {
            acc0 += w[u]; acc1 += w[u + 1]; acc2 += w[u + 2]; acc3 += w[u + 3];
        }
    }
    for (int k = 0; k < cnt_e; k += 16) {
        int e[16];
#pragma unroll
        for (int u = 0; u < 16; u++) e[u] = s_ext[k + u];
        float w[16];
#pragma unroll
        for (int u = 0; u < 16; u++)
            w[u] = (e[u] >= 0) ? __ldg(W_ext + (size_t)e[u] * NN + n) : 0.0f;
#pragma unroll
        for (int u = 0; u < 16; u += 4) {
            acc0 += w[u]; acc1 += w[u + 1]; acc2 += w[u + 2]; acc3 += w[u + 3];
        }
    }

    out[BB * NN + idx] = (acc0 + acc1) + (acc2 + acc3);   // row 1: V_new
}

// ---------------------------------------------------------------------------
extern "C" void kernel_launch(void* const* d_in, const int* in_sizes, int n_in,
                              void* d_out, int out_size) {
    const float* V        = (const float*)d_in[0];   // [B,N]
    const float* a        = (const float*)d_in[1];   // [B,N]
    const float* Xd       = (const float*)d_in[2];   // [D,B,N]
    const float* Xext     = (const float*)d_in[3];   // [DE,B,NE]
    const float* W_int    = (const float*)d_in[4];   // [N,N]
    const float* W_ext    = (const float*)d_in[5];   // [NE,N]
    const float* dmap_int = (const float*)d_in[6];   // [D,N]
    const float* dmap_ext = (const float*)d_in[7];   // [DE,NE]
    float* out = (float*)d_out;                      // [3,B,N]

    k_spike_mask<<<NN / 256, 256>>>(V, a, Xd, Xext, dmap_int, dmap_ext, out);
    k_compact<<<BB, 256>>>();
    dim3 grid(NN / 128, BB);
    k_gather<<<grid, 128>>>(V, W_int, W_ext, out);
}

// round 5
// speedup vs baseline: 1.4638x; 1.4638x over previous
#include <cuda_runtime.h>

// Problem shapes (fixed)
#define BB 32
#define NN 4096
#define DD 8
#define NEE 2048
#define DEE 4

// Device scratch (static globals; no allocation)
__device__ unsigned g_mask_int[NN];
__device__ unsigned g_mask_ext[NEE];
__device__ unsigned char g_del_int[NN];
__device__ unsigned char g_del_ext[NEE];
__device__ int g_list_int[BB][4352];
__device__ int g_list_ext[BB][2304];
__device__ int g_cnt_int[BB];
__device__ int g_cnt_ext[BB];

// ---------------------------------------------------------------------------
// Kernel 1: spike generation (thread per (b,n) element, fully parallel) +
// per-source delay decode + mask zeroing piggybacked on the first N threads.
// X = (V - (1 + 1.8 a) >= 0); a_new = 0.98 a + X. No FMA contraction on the
// threshold path so spike decisions match unfused reference arithmetic.
// ---------------------------------------------------------------------------
__global__ void k_spike(const float* __restrict__ V, const float* __restrict__ a,
                        const float* __restrict__ dmap_int,
                        const float* __restrict__ dmap_ext,
                        float* __restrict__ out) {
    int idx = blockIdx.x * blockDim.x + threadIdx.x;   // 0 .. B*N-1
    float v  = V[idx];
    float aa = a[idx];
    float th = __fadd_rn(1.0f, __fmul_rn(1.8f, aa));
    float x  = (__fadd_rn(v, -th) >= 0.0f) ? 1.0f : 0.0f;
    out[idx] = x;                                       // row 0: X
    out[2 * BB * NN + idx] = 0.98f * aa + x;            // row 2: a_new

    if (idx < NN) {
        int del = 0;
#pragma unroll
        for (int d = 0; d < DD; d++)
            if (dmap_int[d * NN + idx] > 0.5f) del = d;
        g_del_int[idx] = (unsigned char)del;
        g_mask_int[idx] = 0u;
    }
    if (idx < NEE) {
        int del = 0;
#pragma unroll
        for (int d = 0; d < DEE; d++)
            if (dmap_ext[d * NEE + idx] > 0.5f) del = d;
        g_del_ext[idx] = (unsigned char)del;
        g_mask_ext[idx] = 0u;
    }
}

// ---------------------------------------------------------------------------
// Kernel 2: mask build. Warp = (32 consecutive sources, one batch).
// Lane reads its source's delay-selected spike value and atomicOr's its
// batch bit when fired (~5% of lanes). OR is commutative -> deterministic.
// grid: (chunks, B); internal chunks cover N, external piggybacks while
// i < NE.
// ---------------------------------------------------------------------------
__global__ void __launch_bounds__(256) k_mask2(
        const float* __restrict__ Xd, const float* __restrict__ Xext,
        const float* __restrict__ out /* row 0 = X */) {
    int i = blockIdx.x * blockDim.x + threadIdx.x;      // source 0..N-1
    int b = blockIdx.y;                                 // batch

    {
        int del = g_del_int[i];
        float xs = (del == 0) ? out[b * NN + i]
                              : Xd[(size_t)(del - 1) * BB * NN + b * NN + i];
        if (xs > 0.5f) atomicOr(&g_mask_int[i], 1u << b);
    }
    if (i < NEE) {
        int del = g_del_ext[i];
        float xs = Xext[(size_t)del * BB * NEE + b * NEE + i];
        if (xs > 0.5f) atomicOr(&g_mask_ext[i], 1u << b);
    }
}

// ---------------------------------------------------------------------------
// Kernel 3: parallel deterministic compaction. One block (8 warps) per batch.
// Lists padded to a multiple of 16 with -1 sentinels.
// ---------------------------------------------------------------------------
__global__ void __launch_bounds__(256) k_compact() {
    int b = blockIdx.x;            // 0..31
    int tid = threadIdx.x;
    int w = tid >> 5, lane = tid & 31;
    unsigned lt = (lane == 0) ? 0u : (0xffffffffu >> (32 - lane));

    __shared__ int wcnt[8], wbase[8], s_total;

    // ---- internal: each warp owns 512 sources (16 rounds) ----
    {
        int cnt = 0;
#pragma unroll
        for (int r = 0; r < 16; r++) {
            int i = (w * 16 + r) * 32 + lane;
            bool act = (g_mask_int[i] >> b) & 1u;
            cnt += __popc(__ballot_sync(0xffffffffu, act));
        }
        if (lane == 0) wcnt[w] = cnt;
        __syncthreads();
        if (tid == 0) {
            int s = 0;
#pragma unroll
            for (int j = 0; j < 8; j++) { wbase[j] = s; s += wcnt[j]; }
            s_total = s;
        }
        __syncthreads();
        int base = wbase[w];
#pragma unroll
        for (int r = 0; r < 16; r++) {
            int i = (w * 16 + r) * 32 + lane;
            bool act = (g_mask_int[i] >> b) & 1u;
            unsigned bal = __ballot_sync(0xffffffffu, act);
            if (act) g_list_int[b][base + __popc(bal & lt)] = i;
            base += __popc(bal);
        }
        int t = s_total;
        int padded = (t + 15) & ~15;
        if (t + tid < padded) g_list_int[b][t + tid] = -1;
        if (tid == 0) g_cnt_int[b] = padded;
        __syncthreads();
    }

    // ---- external: each warp owns 256 sources (8 rounds) ----
    {
        int cnt = 0;
#pragma unroll
        for (int r = 0; r < 8; r++) {
            int i = (w * 8 + r) * 32 + lane;
            bool act = (g_mask_ext[i] >> b) & 1u;
            cnt += __popc(__ballot_sync(0xffffffffu, act));
        }
        if (lane == 0) wcnt[w] = cnt;
        __syncthreads();
        if (tid == 0) {
            int s = 0;
#pragma unroll
            for (int j = 0; j < 8; j++) { wbase[j] = s; s += wcnt[j]; }
            s_total = s;
        }
        __syncthreads();
        int base = wbase[w];
#pragma unroll
        for (int r = 0; r < 8; r++) {
            int i = (w * 8 + r) * 32 + lane;
            bool act = (g_mask_ext[i] >> b) & 1u;
            unsigned bal = __ballot_sync(0xffffffffu, act);
            if (act) g_list_ext[b][base + __popc(bal & lt)] = i;
            base += __popc(bal);
        }
        int t = s_total;
        int padded = (t + 15) & ~15;
        if (t + tid < padded) g_list_ext[b][t + tid] = -1;
        if (tid == 0) g_cnt_ext[b] = padded;
    }
}

// ---------------------------------------------------------------------------
// Kernel 4: sparse row-gather + membrane update (unchanged from R4: proven
// ~24.5us). One column per thread, launch_bounds(128,4) gives ptxas room to
// keep the full 16-wide LDG window live. 4-way accumulators.
// ---------------------------------------------------------------------------
__global__ void __launch_bounds__(128, 4) k_gather(
        const float* __restrict__ V,
        const float* __restrict__ W_int,
        const float* __restrict__ W_ext,
        float* __restrict__ out) {
    __shared__ int s_int[4352];
    __shared__ int s_ext[2304];

    int b = blockIdx.y;
    const int cnt_i = g_cnt_int[b];
    const int cnt_e = g_cnt_ext[b];
    for (int k = threadIdx.x; k < cnt_i; k += 128) s_int[k] = g_list_int[b][k];
    for (int k = threadIdx.x; k < cnt_e; k += 128) s_ext[k] = g_list_ext[b][k];
    __syncthreads();

    int n = blockIdx.x * 128 + threadIdx.x;   // column
    int idx = b * NN + n;

    float x = out[idx];                       // X (row 0)
    float acc0 = 0.95f * V[idx] * (1.0f - x);
    float acc1 = 0.0f, acc2 = 0.0f, acc3 = 0.0f;

    for (int k = 0; k < cnt_i; k += 16) {
        int e[16];
#pragma unroll
        for (int u = 0; u < 16; u++) e[u] = s_int[k + u];
        float w[16];
#pragma unroll
        for (int u = 0; u < 16; u++)
            w[u] = (e[u] >= 0) ? __ldg(W_int + (size_t)e[u] * NN + n) : 0.0f;
#pragma unroll
        for (int u = 0; u < 16; u += 4) {
            acc0 += w[u]; acc1 += w[u + 1]; acc2 += w[u + 2]; acc3 += w[u + 3];
        }
    }
    for (int k = 0; k < cnt_e; k += 16) {
        int e[16];
#pragma unroll
        for (int u = 0; u < 16; u++) e[u] = s_ext[k + u];
        float w[16];
#pragma unroll
        for (int u = 0; u < 16; u++)
            w[u] = (e[u] >= 0) ? __ldg(W_ext + (size_t)e[u] * NN + n) : 0.0f;
#pragma unroll
        for (int u = 0; u < 16; u += 4) {
            acc0 += w[u]; acc1 += w[u + 1]; acc2 += w[u + 2]; acc3 += w[u + 3];
        }
    }

    out[BB * NN + idx] = (acc0 + acc1) + (acc2 + acc3);   // row 1: V_new
}

// ---------------------------------------------------------------------------
extern "C" void kernel_launch(void* const* d_in, const int* in_sizes, int n_in,
                              void* d_out, int out_size) {
    const float* V        = (const float*)d_in[0];   // [B,N]
    const float* a        = (const float*)d_in[1];   // [B,N]
    const float* Xd       = (const float*)d_in[2];   // [D,B,N]
    const float* Xext     = (const float*)d_in[3];   // [DE,B,NE]
    const float* W_int    = (const float*)d_in[4];   // [N,N]
    const float* W_ext    = (const float*)d_in[5];   // [NE,N]
    const float* dmap_int = (const float*)d_in[6];   // [D,N]
    const float* dmap_ext = (const float*)d_in[7];   // [DE,NE]
    float* out = (float*)d_out;                      // [3,B,N]

    k_spike<<<(BB * NN) / 256, 256>>>(V, a, dmap_int, dmap_ext, out);
    dim3 mgrid(NN / 256, BB);
    k_mask2<<<mgrid, 256>>>(Xd, Xext, out);
    k_compact<<<BB, 256>>>();
    dim3 grid(NN / 128, BB);
    k_gather<<<grid, 128>>>(V, W_int, W_ext, out);
}